// round 2
// baseline (speedup 1.0000x reference)
#include <cuda_runtime.h>
#include <math.h>

#define BB 16
#define HH 56
#define WW 56
#define CC 128
#define HW 3136
#define NELEM (BB*HW*CC)   // 6422528
#define CH 8               // channels per block in main kernel
#define CST 3300           // padded per-channel SAT stride (floats); 3300 % 32 == 4

// ---------------- device scratch (no allocation allowed) ----------------
__device__ float    g_t1[NELEM];
__device__ float    g_t2[NELEM];
__device__ float    g_squeeze[BB*CC];
__device__ float    g_excite[BB*CC];
__device__ unsigned g_mm[2*BB];     // [0..15] min-enc, [16..31] max-enc
__device__ float    g_bv[5];
__device__ float    g_nbv;

// order-preserving float <-> uint encoding for atomic min/max
__device__ __forceinline__ unsigned fenc(float f){
    unsigned u = __float_as_uint(f);
    return (u & 0x80000000u) ? ~u : (u | 0x80000000u);
}
__device__ __forceinline__ float fdec(unsigned u){
    unsigned b = (u & 0x80000000u) ? (u & 0x7fffffffu) : ~u;
    return __uint_as_float(b);
}

// ---------------- kernel 0: init scratch + scale constants ----------------
__global__ void k_init(const float* __restrict__ kappa){
    int t = threadIdx.x;
    if (t < BB)           g_mm[t] = 0xFFFFFFFFu;   // min
    else if (t < 2*BB)    g_mm[t] = 0u;            // max
    if (t == 0){
        const float LN2 = 0.6931471805599453f;
        float v[5]; float mean = 0.f;
        for (int s = 0; s < 5; s++){
            float kk   = 1.f/(1.f + expf(-kappa[s]));
            float lk   = logf(kk + 1e-7f);
            float logk = 1.f/(1.f + expf(-lk));
            v[s] = logk + (float)(s+1)*LN2;        // log_k + log_r
            mean += v[s];
        }
        mean *= 0.2f;
        float n2 = 0.f;
        for (int s = 0; s < 5; s++){ float bv = v[s]-mean; g_bv[s] = bv; n2 += bv*bv; }
        g_nbv = sqrtf(n2);
    }
}

// ---------------- kernel A: per-batch min/max ----------------
__global__ void k_minmax(const float* __restrict__ x){
    int b = blockIdx.x >> 4, sub = blockIdx.x & 15;
    const float4* xb = (const float4*)(x + (size_t)b*HW*CC);
    const int n4 = HW*CC/4;   // 100352
    float mn = 3.4e38f, mx = -3.4e38f;
    for (int i = sub*256 + threadIdx.x; i < n4; i += 16*256){
        float4 v = xb[i];
        mn = fminf(mn, fminf(fminf(v.x,v.y), fminf(v.z,v.w)));
        mx = fmaxf(mx, fmaxf(fmaxf(v.x,v.y), fmaxf(v.z,v.w)));
    }
    #pragma unroll
    for (int o = 16; o; o >>= 1){
        mn = fminf(mn, __shfl_xor_sync(~0u, mn, o));
        mx = fmaxf(mx, __shfl_xor_sync(~0u, mx, o));
    }
    __shared__ float smn[8], smx[8];
    int lane = threadIdx.x & 31, wp = threadIdx.x >> 5;
    if (lane == 0){ smn[wp] = mn; smx[wp] = mx; }
    __syncthreads();
    if (threadIdx.x == 0){
        for (int i = 1; i < 8; i++){ mn = fminf(mn, smn[i]); mx = fmaxf(mx, smx[i]); }
        atomicMin(&g_mm[b],     fenc(mn));
        atomicMax(&g_mm[BB+b],  fenc(mx));
    }
}

// ---------------- kernel B: SAT + alphas + sim, emit t1/t2 + squeeze ----------------
__global__ void __launch_bounds__(256) k_main(
    const float* __restrict__ x,
    const float* __restrict__ gamma, const float* __restrict__ beta,
    const float* __restrict__ bn_mean, const float* __restrict__ bn_var)
{
    extern __shared__ float sat[];      // CH * CST floats
    int b  = blockIdx.y;
    int c0 = blockIdx.x * CH;
    int t  = threadIdx.x;               // 256
    int ci = t & 7;
    int c  = c0 + ci;

    float xmin = fdec(g_mm[b]);
    float xmax = fdec(g_mm[BB+b]);
    float inv  = 1.f/(xmax - xmin + 1e-7f);
    const float* xb = x + (size_t)b*HW*CC;

    // zero SAT borders (row 0, col 0 of each 57x57 table)
    for (int i = t; i < CH*57; i += 256){
        int cc = i/57, j = i%57;
        sat[cc*CST + j]      = 0.f;     // row 0
        sat[cc*CST + j*57]   = 0.f;     // col 0
    }
    // load normalized xs into SAT interior (coalesced: 8 consecutive channels per pixel)
    for (int idx = t; idx < HW*CH; idx += 256){
        int cc = idx & 7; int p = idx >> 3;
        int h = p/56, w = p - h*56;
        float v = (xb[p*CC + c0 + cc] - xmin) * inv;
        sat[cc*CST + (h+1)*57 + (w+1)] = v;
    }
    __syncthreads();

    // row prefix sums (448 rows)
    for (int r = t; r < 448; r += 256){
        int cc = r/56; int i = (r%56) + 1;
        float* row = sat + cc*CST + i*57;
        float acc = 0.f;
        #pragma unroll
        for (int j = 1; j <= 56; j++){ acc += row[j]; row[j] = acc; }
    }
    __syncthreads();

    // column prefix sums (448 cols)
    for (int r = t; r < 448; r += 256){
        int cc = r/56; int j = (r%56) + 1;
        float* col = sat + cc*CST + j;
        float acc = 0.f;
        #pragma unroll
        for (int i = 1; i <= 56; i++){ acc += col[i*57]; col[i*57] = acc; }
    }
    __syncthreads();

    // per-thread constants
    float bns = gamma[c] * rsqrtf(bn_var[c] + 1e-3f);
    float bnb = beta[c] - bns*bn_mean[c];
    float bv0 = g_bv[0], bv1 = g_bv[1], bv2 = g_bv[2], bv3 = g_bv[3], bv4 = g_bv[4];
    float nbv = g_nbv;
    const float* S = sat + ci*CST;
    float* t1p = g_t1 + (size_t)b*HW*CC;
    float* t2p = g_t2 + (size_t)b*HW*CC;

    float asum = 0.f;
    int p0 = t >> 3;
    const int KK[5] = {2,4,8,16,32};
    const int PB[5] = {0,1,3,7,15};   // TF SAME pad_before = (k-1)/2

    for (int it = 0; it < 98; it++){
        int p = p0 + it*32;
        int h = p/56, w = p - h*56;
        float lm[5];
        #pragma unroll
        for (int s = 0; s < 5; s++){
            int r0 = max(h - PB[s], 0), r1 = min(h - PB[s] + KK[s], 56);
            int q0 = max(w - PB[s], 0), q1 = min(w - PB[s] + KK[s], 56);
            float m = S[r1*57 + q1] - S[r0*57 + q1] - S[r1*57 + q0] + S[r0*57 + q0];
            lm[s] = __logf(m + 1e-7f);
        }
        float mean = 0.2f*(lm[0]+lm[1]+lm[2]+lm[3]+lm[4]);
        float a0 = lm[0]-mean, a1 = lm[1]-mean, a2 = lm[2]-mean, a3 = lm[3]-mean, a4 = lm[4]-mean;
        // alpha = sum(lm * xc)/sum(xc^2), xc = ln2*{-2,-1,0,1,2}
        float alpha = 0.14426950408889634f * (2.f*(lm[4]-lm[0]) + (lm[3]-lm[1]));
        float na2 = a0*a0 + a1*a1 + a2*a2 + a3*a3 + a4*a4;
        float dotv = a0*bv0 + a1*bv1 + a2*bv2 + a3*bv3 + a4*bv4;
        float denom = sqrtf(na2) * fabsf(alpha) * nbv + 1e-7f;
        float cosv = alpha * dotv / denom;
        float sim  = 0.5f*cosv + 0.5f;
        float sg   = 1.f/(1.f + __expf(-(bns*alpha + bnb)));   // sigmoid(BN(alpha))
        float xs   = (__ldg(&xb[p*CC + c]) - xmin) * inv;      // L2 hit: x re-read
        int o = p*CC + c;
        t1p[o] = sim * sg;
        t2p[o] = (1.f - sim) * xs;
        asum += alpha;
    }

    // per-channel alpha sum -> squeeze (block owns full H*W of its 8 channels)
    asum += __shfl_xor_sync(~0u, asum, 8);
    asum += __shfl_xor_sync(~0u, asum, 16);
    __shared__ float red[8][8];
    int lane = t & 31, wp = t >> 5;
    if (lane < 8) red[wp][lane] = asum;
    __syncthreads();
    if (t < 8){
        float s = 0.f;
        #pragma unroll
        for (int i = 0; i < 8; i++) s += red[i][t];
        g_squeeze[b*CC + c0 + t] = s * (1.f/3136.f);
    }
}

// ---------------- kernel C: SE-MLP -> excite ----------------
__global__ void k_excite(const float* __restrict__ W1, const float* __restrict__ b1,
                         const float* __restrict__ W2, const float* __restrict__ b2)
{
    __shared__ float hid[BB][16];
    int t = threadIdx.x;              // 256 = 16 batches x 16 hidden
    int bb = t >> 4, j = t & 15;
    float acc = b1[j];
    for (int cc = 0; cc < CC; cc++) acc += g_squeeze[bb*CC + cc] * W1[cc*16 + j];
    hid[bb][j] = fmaxf(acc, 0.f);
    __syncthreads();
    for (int i = t; i < BB*CC; i += 256){
        int b2i = i >> 7, cc = i & 127;
        float a = b2[cc];
        #pragma unroll
        for (int jj = 0; jj < 16; jj++) a += hid[b2i][jj] * W2[jj*CC + cc];
        g_excite[i] = 1.f/(1.f + __expf(-a));
    }
}

// ---------------- kernel D: final blend ----------------
__global__ void k_final(float* __restrict__ out){
    int i = blockIdx.x*blockDim.x + threadIdx.x;   // float4 index
    const int N4 = NELEM/4;                        // 1605632
    if (i >= N4) return;
    float4 a = ((const float4*)g_t1)[i];
    float4 d = ((const float4*)g_t2)[i];
    int c4 = i & 31;
    int bb = i / (HW*32);
    float4 e = ((const float4*)g_excite)[bb*32 + c4];
    float4 o;
    o.x = fmaf(d.x, e.x, a.x);
    o.y = fmaf(d.y, e.y, a.y);
    o.z = fmaf(d.z, e.z, a.z);
    o.w = fmaf(d.w, e.w, a.w);
    ((float4*)out)[i] = o;
}

// ---------------- launch ----------------
extern "C" void kernel_launch(void* const* d_in, const int* in_sizes, int n_in,
                              void* d_out, int out_size)
{
    const float* x       = (const float*)d_in[0];
    const float* kappa   = (const float*)d_in[1];
    const float* W1      = (const float*)d_in[2];
    const float* b1      = (const float*)d_in[3];
    const float* W2      = (const float*)d_in[4];
    const float* b2      = (const float*)d_in[5];
    const float* gamma   = (const float*)d_in[6];
    const float* beta    = (const float*)d_in[7];
    const float* bn_mean = (const float*)d_in[8];
    const float* bn_var  = (const float*)d_in[9];

    cudaFuncSetAttribute(k_main, cudaFuncAttributeMaxDynamicSharedMemorySize, CH*CST*4);

    k_init<<<1, 32>>>(kappa);
    k_minmax<<<256, 256>>>(x);
    dim3 gb(CC/CH, BB);
    k_main<<<gb, 256, CH*CST*4>>>(x, gamma, beta, bn_mean, bn_var);
    k_excite<<<1, 256>>>(W1, b1, W2, b2);
    k_final<<<(NELEM/4 + 255)/256, 256>>>((float*)d_out);
}

// round 3
// speedup vs baseline: 1.0026x; 1.0026x over previous
#include <cuda_runtime.h>
#include <math.h>

#define BB 16
#define HH 56
#define WW 56
#define CC 128
#define HW 3136
#define NELEM (BB*HW*CC)   // 6422528
#define CH 8               // channels per block in main kernel
#define CST 3300           // padded per-channel SAT stride (floats); 3300 % 32 == 4

// ---------------- device scratch (no allocation allowed) ----------------
__device__ float g_t1[NELEM];
__device__ float g_t2[NELEM];
__device__ float g_squeeze[BB*CC];
__device__ float g_pmin[BB*16];
__device__ float g_pmax[BB*16];
__device__ float g_bv[5];
__device__ float g_nbv;

// ---------------- fast log2 on the FMA pipe (cephes-grade) ----------------
__device__ __forceinline__ float fast_log2(float x){
    int xi = __float_as_int(x);
    int e  = ((xi >> 23) & 0xff) - 127;
    float m = __int_as_float((xi & 0x7fffff) | 0x3f800000);   // [1,2)
    if (m > 1.41421356f){ m *= 0.5f; e += 1; }                // -> [0.7071,1.4142]
    float t = m - 1.0f;                                       // [-0.2929,0.4142]
    float z = t*t;
    float p =              7.0376836292e-2f;
    p = fmaf(p, t, -1.1514610310e-1f);
    p = fmaf(p, t,  1.1676998740e-1f);
    p = fmaf(p, t, -1.2420140846e-1f);
    p = fmaf(p, t,  1.4249322787e-1f);
    p = fmaf(p, t, -1.6668057665e-1f);
    p = fmaf(p, t,  2.0000714765e-1f);
    p = fmaf(p, t, -2.4999993993e-1f);
    p = fmaf(p, t,  3.3333331174e-1f);
    float ln = fmaf(t*z, p, fmaf(-0.5f, z, t));               // ln(1+t)
    return fmaf(ln, 1.4426950408889634f, (float)e);           // log2(x)
}

// ---------------- kernel A: per-batch partial min/max + scale constants ----------------
__global__ void k_minmax(const float* __restrict__ x, const float* __restrict__ kappa){
    int b = blockIdx.x >> 4, sub = blockIdx.x & 15;
    const float4* xb = (const float4*)(x + (size_t)b*HW*CC);
    const int n4 = HW*CC/4;   // 100352
    float mn = 3.4e38f, mx = -3.4e38f;
    for (int i = sub*256 + threadIdx.x; i < n4; i += 16*256){
        float4 v = xb[i];
        mn = fminf(mn, fminf(fminf(v.x,v.y), fminf(v.z,v.w)));
        mx = fmaxf(mx, fmaxf(fmaxf(v.x,v.y), fmaxf(v.z,v.w)));
    }
    #pragma unroll
    for (int o = 16; o; o >>= 1){
        mn = fminf(mn, __shfl_xor_sync(~0u, mn, o));
        mx = fmaxf(mx, __shfl_xor_sync(~0u, mx, o));
    }
    __shared__ float smn[8], smx[8];
    int lane = threadIdx.x & 31, wp = threadIdx.x >> 5;
    if (lane == 0){ smn[wp] = mn; smx[wp] = mx; }
    __syncthreads();
    if (threadIdx.x == 0){
        for (int i = 1; i < 8; i++){ mn = fminf(mn, smn[i]); mx = fmaxf(mx, smx[i]); }
        g_pmin[b*16+sub] = mn;
        g_pmax[b*16+sub] = mx;
    }
    // one thread anywhere computes the kappa-derived scale constants
    if (blockIdx.x == 0 && threadIdx.x == 32){
        const float LN2 = 0.6931471805599453f;
        float v[5]; float mean = 0.f;
        for (int s = 0; s < 5; s++){
            float kk   = 1.f/(1.f + expf(-kappa[s]));
            float lk   = logf(kk + 1e-7f);
            float logk = 1.f/(1.f + expf(-lk));
            v[s] = logk + (float)(s+1)*LN2;        // log_k + log_r
            mean += v[s];
        }
        mean *= 0.2f;
        float n2 = 0.f;
        for (int s = 0; s < 5; s++){ float bv = v[s]-mean; g_bv[s] = bv; n2 += bv*bv; }
        g_nbv = sqrtf(n2);
    }
}

// ---------------- kernel B: SAT + alphas + sim, emit t1/t2 + squeeze ----------------
__global__ void __launch_bounds__(256) k_main(
    const float* __restrict__ x,
    const float* __restrict__ gamma, const float* __restrict__ beta,
    const float* __restrict__ bn_mean, const float* __restrict__ bn_var)
{
    extern __shared__ float sat[];      // CH * CST floats
    int b  = blockIdx.y;
    int c0 = blockIdx.x * CH;
    int t  = threadIdx.x;               // 256
    int ci = t & 7;
    int c  = c0 + ci;

    // reduce the 16 partial min/max for this batch
    __shared__ float s_mm[2];
    {
        float v  = (t < 16) ? g_pmin[b*16 + t] : ((t < 32) ? g_pmax[b*16 + (t-16)] : 0.f);
        if (t < 32){
            float mnv = (t < 16) ? v :  3.4e38f;
            float mxv = (t >= 16) ? v : -3.4e38f;
            #pragma unroll
            for (int o = 16; o; o >>= 1){
                mnv = fminf(mnv, __shfl_xor_sync(~0u, mnv, o));
                mxv = fmaxf(mxv, __shfl_xor_sync(~0u, mxv, o));
            }
            if (t == 0){ s_mm[0] = mnv; s_mm[1] = mxv; }
        }
    }
    __syncthreads();
    float xmin = s_mm[0];
    float xmax = s_mm[1];
    float inv  = 1.f/(xmax - xmin + 1e-7f);
    const float* xb = x + (size_t)b*HW*CC;

    // zero SAT borders (row 0, col 0 of each 57x57 table)
    for (int i = t; i < CH*57; i += 256){
        int cc = i/57, j = i%57;
        sat[cc*CST + j]      = 0.f;     // row 0
        sat[cc*CST + j*57]   = 0.f;     // col 0
    }
    // load normalized xs into SAT interior (coalesced: 8 consecutive channels per pixel)
    for (int idx = t; idx < HW*CH; idx += 256){
        int cc = idx & 7; int p = idx >> 3;
        int h = p/56, w = p - h*56;
        float v = (xb[p*CC + c0 + cc] - xmin) * inv;
        sat[cc*CST + (h+1)*57 + (w+1)] = v;
    }
    __syncthreads();

    // row prefix sums (448 rows)
    for (int r = t; r < 448; r += 256){
        int cc = r/56; int i = (r%56) + 1;
        float* row = sat + cc*CST + i*57;
        float acc = 0.f;
        #pragma unroll
        for (int j = 1; j <= 56; j++){ acc += row[j]; row[j] = acc; }
    }
    __syncthreads();

    // column prefix sums (448 cols)
    for (int r = t; r < 448; r += 256){
        int cc = r/56; int j = (r%56) + 1;
        float* col = sat + cc*CST + j;
        float acc = 0.f;
        #pragma unroll
        for (int i = 1; i <= 56; i++){ acc += col[i*57]; col[i*57] = acc; }
    }
    __syncthreads();

    // per-thread constants
    float bns = gamma[c] * rsqrtf(bn_var[c] + 1e-3f);
    float bnb = beta[c] - bns*bn_mean[c];
    float bv0 = g_bv[0], bv1 = g_bv[1], bv2 = g_bv[2], bv3 = g_bv[3], bv4 = g_bv[4];
    float nbv = g_nbv;
    const float* S = sat + ci*CST;
    float* t1p = g_t1 + (size_t)b*HW*CC;
    float* t2p = g_t2 + (size_t)b*HW*CC;

    const float LN2 = 0.69314718055994531f;
    float asum = 0.f;
    int p0 = t >> 3;
    const int KK[5] = {2,4,8,16,32};
    const int PB[5] = {0,1,3,7,15};   // TF SAME pad_before = (k-1)/2

    for (int it = 0; it < 98; it++){
        int p = p0 + it*32;
        int h = p/56, w = p - h*56;
        float L[5];   // log2(m + eps)
        #pragma unroll
        for (int s = 0; s < 5; s++){
            int r0 = max(h - PB[s], 0), r1 = min(h - PB[s] + KK[s], 56);
            int q0 = max(w - PB[s], 0), q1 = min(w - PB[s] + KK[s], 56);
            float m = S[r1*57 + q1] - S[r0*57 + q1] - S[r1*57 + q0] + S[r0*57 + q0];
            L[s] = fast_log2(m + 1e-7f);
        }
        float mean = 0.2f*(L[0]+L[1]+L[2]+L[3]+L[4]);
        float a0 = L[0]-mean, a1 = L[1]-mean, a2 = L[2]-mean, a3 = L[3]-mean, a4 = L[4]-mean;
        // alpha (natural-log OLS slope) == 0.1*(2(L4-L0)+(L3-L1)) in log2 basis
        float alpha = 0.1f * (2.f*(L[4]-L[0]) + (L[3]-L[1]));
        float na2  = a0*a0 + a1*a1 + a2*a2 + a3*a3 + a4*a4;
        float dotv = a0*bv0 + a1*bv1 + a2*bv2 + a3*bv3 + a4*bv4;
        // natural-basis vectors are ln2 * (log2 vectors); keep ln2 around the eps
        float denom = sqrtf(na2)*LN2 * fabsf(alpha) * nbv + 1e-7f;
        float cosv  = __fdividef(alpha * dotv * LN2, denom);
        float sim   = 0.5f*cosv + 0.5f;
        float sg    = __fdividef(1.f, 1.f + __expf(-(bns*alpha + bnb)));  // sigmoid(BN(alpha))
        float xs    = (__ldg(&xb[p*CC + c]) - xmin) * inv;                // L2-hit re-read
        int o = p*CC + c;
        t1p[o] = sim * sg;
        t2p[o] = (1.f - sim) * xs;
        asum += alpha;
    }

    // per-channel alpha sum -> squeeze (block owns full H*W of its 8 channels)
    asum += __shfl_xor_sync(~0u, asum, 8);
    asum += __shfl_xor_sync(~0u, asum, 16);
    __shared__ float red[8][8];
    int lane = t & 31, wp = t >> 5;
    if (lane < 8) red[wp][lane] = asum;
    __syncthreads();
    if (t < 8){
        float s = 0.f;
        #pragma unroll
        for (int i = 0; i < 8; i++) s += red[i][t];
        g_squeeze[b*CC + c0 + t] = s * (1.f/3136.f);
    }
}

// ---------------- kernel C: per-block SE-MLP (smem) + final blend ----------------
__global__ void __launch_bounds__(256) k_final(
    float* __restrict__ out,
    const float* __restrict__ W1, const float* __restrict__ b1,
    const float* __restrict__ W2, const float* __restrict__ b2)
{
    // each block covers 1024 float4 = 4096 floats; batch slab = 100352 float4 = 98 blocks
    int blk = blockIdx.x;
    int b   = blk / 98;
    int t   = threadIdx.x;

    __shared__ float s_sq[CC];
    __shared__ float s_hid[16];
    __shared__ float s_exc[CC];

    if (t < CC) s_sq[t] = g_squeeze[b*CC + t];
    __syncthreads();

    // hidden[j] = relu(b1[j] + sum_c sq[c]*W1[c*16+j]); 256 thr = (j<16) x (cl<16)
    {
        int j = t >> 4, cl = t & 15;
        float acc = 0.f;
        #pragma unroll
        for (int k = 0; k < 8; k++){
            int cc = cl + 16*k;
            acc += s_sq[cc] * __ldg(&W1[cc*16 + j]);
        }
        #pragma unroll
        for (int o = 8; o; o >>= 1) acc += __shfl_xor_sync(~0u, acc, o);
        if (cl == 0) s_hid[j] = fmaxf(acc + __ldg(&b1[j]), 0.f);
    }
    __syncthreads();

    if (t < CC){
        float a = __ldg(&b2[t]);
        #pragma unroll
        for (int j = 0; j < 16; j++) a += s_hid[j] * __ldg(&W2[j*CC + t]);
        s_exc[t] = __fdividef(1.f, 1.f + __expf(-a));
    }
    __syncthreads();

    const float4* exc4 = (const float4*)s_exc;
    #pragma unroll
    for (int it = 0; it < 4; it++){
        int i = blk*1024 + it*256 + t;      // float4 index
        float4 a = ((const float4*)g_t1)[i];
        float4 d = ((const float4*)g_t2)[i];
        float4 e = exc4[i & 31];
        float4 o;
        o.x = fmaf(d.x, e.x, a.x);
        o.y = fmaf(d.y, e.y, a.y);
        o.z = fmaf(d.z, e.z, a.z);
        o.w = fmaf(d.w, e.w, a.w);
        ((float4*)out)[i] = o;
    }
}

// ---------------- launch ----------------
extern "C" void kernel_launch(void* const* d_in, const int* in_sizes, int n_in,
                              void* d_out, int out_size)
{
    const float* x       = (const float*)d_in[0];
    const float* kappa   = (const float*)d_in[1];
    const float* W1      = (const float*)d_in[2];
    const float* b1      = (const float*)d_in[3];
    const float* W2      = (const float*)d_in[4];
    const float* b2      = (const float*)d_in[5];
    const float* gamma   = (const float*)d_in[6];
    const float* beta    = (const float*)d_in[7];
    const float* bn_mean = (const float*)d_in[8];
    const float* bn_var  = (const float*)d_in[9];

    cudaFuncSetAttribute(k_main, cudaFuncAttributeMaxDynamicSharedMemorySize, CH*CST*4);

    k_minmax<<<256, 256>>>(x, kappa);
    dim3 gb(CC/CH, BB);
    k_main<<<gb, 256, CH*CST*4>>>(x, gamma, beta, bn_mean, bn_var);
    k_final<<<NELEM/4096, 256>>>((float*)d_out, W1, b1, W2, b2);
}

// round 6
// speedup vs baseline: 1.0729x; 1.0701x over previous
#include <cuda_runtime.h>
#include <math.h>

#define BB 16
#define HH 56
#define WW 56
#define CC 128
#define HW 3136
#define NELEM (BB*HW*CC)   // 6422528
#define CH 8               // channels per block in main kernel
#define CST 3300           // padded per-channel SAT stride (floats); 3300 % 32 == 4

// ---------------- device scratch (no allocation allowed) ----------------
__device__ float2 g_t12[NELEM];       // interleaved (t1, t2)
__device__ float  g_squeeze[BB*CC];
__device__ float  g_pmin[BB*32];
__device__ float  g_pmax[BB*32];
__device__ float  g_bv[5];
__device__ float  g_nbv;

// ---------------- fast log2 on the FMA pipe (cephes-grade) ----------------
__device__ __forceinline__ float fast_log2(float x){
    int xi = __float_as_int(x);
    int e  = ((xi >> 23) & 0xff) - 127;
    float m = __int_as_float((xi & 0x7fffff) | 0x3f800000);   // [1,2)
    if (m > 1.41421356f){ m *= 0.5f; e += 1; }                // -> [0.7071,1.4142]
    float t = m - 1.0f;
    float z = t*t;
    float p =              7.0376836292e-2f;
    p = fmaf(p, t, -1.1514610310e-1f);
    p = fmaf(p, t,  1.1676998740e-1f);
    p = fmaf(p, t, -1.2420140846e-1f);
    p = fmaf(p, t,  1.4249322787e-1f);
    p = fmaf(p, t, -1.6668057665e-1f);
    p = fmaf(p, t,  2.0000714765e-1f);
    p = fmaf(p, t, -2.4999993993e-1f);
    p = fmaf(p, t,  3.3333331174e-1f);
    float ln = fmaf(t*z, p, fmaf(-0.5f, z, t));               // ln(1+t)
    return fmaf(ln, 1.4426950408889634f, (float)e);           // log2(x)
}

// ---------------- kernel A: per-batch partial min/max + scale constants ----------------
__global__ void __launch_bounds__(256) k_minmax(const float* __restrict__ x,
                                                const float* __restrict__ kappa){
    int b = blockIdx.x >> 5, sub = blockIdx.x & 31;
    const float4* xb = (const float4*)(x + (size_t)b*HW*CC);
    const int n4 = HW*CC/4;   // 100352
    // 8-way ILP: independent accumulators per float4 component
    float mn0=3.4e38f, mn1=3.4e38f, mn2=3.4e38f, mn3=3.4e38f;
    float mx0=-3.4e38f, mx1=-3.4e38f, mx2=-3.4e38f, mx3=-3.4e38f;
    for (int i = sub*256 + threadIdx.x; i < n4; i += 32*256){
        float4 v = xb[i];
        mn0 = fminf(mn0, v.x); mx0 = fmaxf(mx0, v.x);
        mn1 = fminf(mn1, v.y); mx1 = fmaxf(mx1, v.y);
        mn2 = fminf(mn2, v.z); mx2 = fmaxf(mx2, v.z);
        mn3 = fminf(mn3, v.w); mx3 = fmaxf(mx3, v.w);
    }
    float mn = fminf(fminf(mn0,mn1), fminf(mn2,mn3));
    float mx = fmaxf(fmaxf(mx0,mx1), fmaxf(mx2,mx3));
    #pragma unroll
    for (int o = 16; o; o >>= 1){
        mn = fminf(mn, __shfl_xor_sync(~0u, mn, o));
        mx = fmaxf(mx, __shfl_xor_sync(~0u, mx, o));
    }
    __shared__ float smn[8], smx[8];
    int lane = threadIdx.x & 31, wp = threadIdx.x >> 5;
    if (lane == 0){ smn[wp] = mn; smx[wp] = mx; }
    __syncthreads();
    if (threadIdx.x == 0){
        for (int i = 1; i < 8; i++){ mn = fminf(mn, smn[i]); mx = fmaxf(mx, smx[i]); }
        g_pmin[b*32+sub] = mn;
        g_pmax[b*32+sub] = mx;
    }
    if (blockIdx.x == 0 && threadIdx.x == 32){
        const float LN2 = 0.6931471805599453f;
        float v[5]; float mean = 0.f;
        for (int s = 0; s < 5; s++){
            float kk   = 1.f/(1.f + expf(-kappa[s]));
            float lk   = logf(kk + 1e-7f);
            float logk = 1.f/(1.f + expf(-lk));
            v[s] = logk + (float)(s+1)*LN2;        // log_k + log_r
            mean += v[s];
        }
        mean *= 0.2f;
        float n2 = 0.f;
        for (int s = 0; s < 5; s++){ float bv = v[s]-mean; g_bv[s] = bv; n2 += bv*bv; }
        g_nbv = sqrtf(n2);
    }
}

// ---------------- kernel B: SAT + alphas + sim, emit t12 + squeeze ----------------
__global__ void __launch_bounds__(512) k_main(
    const float* __restrict__ x,
    const float* __restrict__ gamma, const float* __restrict__ beta,
    const float* __restrict__ bn_mean, const float* __restrict__ bn_var)
{
    extern __shared__ float sat[];      // CH * CST floats
    int b  = blockIdx.y;
    int c0 = blockIdx.x * CH;
    int t  = threadIdx.x;               // 512
    int ci = t & 7;
    int c  = c0 + ci;

    // reduce the 32 partial min/max for this batch (warp 0)
    __shared__ float s_mm[2];
    if (t < 32){
        float mnv = g_pmin[b*32 + t];
        float mxv = g_pmax[b*32 + t];
        #pragma unroll
        for (int o = 16; o; o >>= 1){
            mnv = fminf(mnv, __shfl_xor_sync(~0u, mnv, o));
            mxv = fmaxf(mxv, __shfl_xor_sync(~0u, mxv, o));
        }
        if (t == 0){ s_mm[0] = mnv; s_mm[1] = mxv; }
    }
    // zero SAT borders (row 0, col 0 of each 57x57 table); CH*57 = 456 < 512
    if (t < CH*57){
        int cc = t/57, j = t%57;
        sat[cc*CST + j]      = 0.f;     // row 0
        sat[cc*CST + j*57]   = 0.f;     // col 0
    }
    __syncthreads();
    float xmin = s_mm[0];
    float xmax = s_mm[1];
    float inv  = 1.f/(xmax - xmin + 1e-7f);
    const float* xb = x + (size_t)b*HW*CC;

    // load normalized xs into SAT interior (coalesced: 8 consecutive channels per pixel)
    for (int idx = t; idx < HW*CH; idx += 512){
        int cc = idx & 7; int p = idx >> 3;
        int h = p/56, w = p - h*56;
        float v = (xb[p*CC + c0 + cc] - xmin) * inv;
        sat[cc*CST + (h+1)*57 + (w+1)] = v;
    }
    __syncthreads();

    // row prefix sums (448 rows, one per thread)
    if (t < 448){
        int cc = t/56; int i = (t%56) + 1;
        float* row = sat + cc*CST + i*57;
        float acc = 0.f;
        #pragma unroll
        for (int j = 1; j <= 56; j++){ acc += row[j]; row[j] = acc; }
    }
    __syncthreads();

    // column prefix sums (448 cols, one per thread)
    if (t < 448){
        int cc = t/56; int j = (t%56) + 1;
        float* col = sat + cc*CST + j;
        float acc = 0.f;
        #pragma unroll
        for (int i = 1; i <= 56; i++){ acc += col[i*57]; col[i*57] = acc; }
    }
    __syncthreads();

    // per-thread constants
    float bns = gamma[c] * rsqrtf(bn_var[c] + 1e-3f);
    float bnb = beta[c] - bns*bn_mean[c];
    float bv0 = g_bv[0], bv1 = g_bv[1], bv2 = g_bv[2], bv3 = g_bv[3], bv4 = g_bv[4];
    float nbv = g_nbv;
    const float* S = sat + ci*CST;
    float2* t12p = g_t12 + (size_t)b*HW*CC;

    const float LN2 = 0.69314718055994531f;
    float asum = 0.f;
    int p0 = t >> 3;                   // 0..63
    const int KK[5] = {2,4,8,16,32};
    const int PB[5] = {0,1,3,7,15};    // TF SAME pad_before = (k-1)/2

    for (int it = 0; it < 49; it++){
        int p = p0 + it*64;
        int h = p/56, w = p - h*56;
        float L[5];   // log2(m + eps)
        #pragma unroll
        for (int s = 0; s < 5; s++){
            int r0 = max(h - PB[s], 0), r1 = min(h - PB[s] + KK[s], 56);
            int q0 = max(w - PB[s], 0), q1 = min(w - PB[s] + KK[s], 56);
            float m = S[r1*57 + q1] - S[r0*57 + q1] - S[r1*57 + q0] + S[r0*57 + q0];
            L[s] = fast_log2(m + 1e-7f);
        }
        float mean = 0.2f*(L[0]+L[1]+L[2]+L[3]+L[4]);
        float a0 = L[0]-mean, a1 = L[1]-mean, a2 = L[2]-mean, a3 = L[3]-mean, a4 = L[4]-mean;
        // alpha (natural-log OLS slope) == 0.1*(2(L4-L0)+(L3-L1)) in log2 basis
        float alpha = 0.1f * (2.f*(L[4]-L[0]) + (L[3]-L[1]));
        float na2  = a0*a0 + a1*a1 + a2*a2 + a3*a3 + a4*a4;
        float dotv = a0*bv0 + a1*bv1 + a2*bv2 + a3*bv3 + a4*bv4;
        float denom = sqrtf(na2)*LN2 * fabsf(alpha) * nbv + 1e-7f;
        float cosv  = __fdividef(alpha * dotv * LN2, denom);
        float sim   = 0.5f*cosv + 0.5f;
        float sg    = __fdividef(1.f, 1.f + __expf(-(bns*alpha + bnb)));  // sigmoid(BN(alpha))
        float xs    = (__ldg(&xb[p*CC + c]) - xmin) * inv;                // L2-hit re-read
        t12p[p*CC + c] = make_float2(sim * sg, (1.f - sim) * xs);
        asum += alpha;
    }

    // per-channel alpha sum -> squeeze (block owns full H*W of its 8 channels)
    // within warp: 4 pixel-groups (lane>>3); reduce over them
    asum += __shfl_xor_sync(~0u, asum, 8);
    asum += __shfl_xor_sync(~0u, asum, 16);
    __shared__ float red[16][8];
    int lane = t & 31, wp = t >> 5;
    if (lane < 8) red[wp][lane] = asum;
    __syncthreads();
    if (t < 8){
        float s = 0.f;
        #pragma unroll
        for (int i = 0; i < 16; i++) s += red[i][t];
        g_squeeze[b*CC + c0 + t] = s * (1.f/3136.f);
    }
}

// ---------------- kernel C: per-block SE-MLP (smem) + final blend ----------------
__global__ void __launch_bounds__(256) k_final(
    float* __restrict__ out,
    const float* __restrict__ W1, const float* __restrict__ b1,
    const float* __restrict__ W2, const float* __restrict__ b2)
{
    // each block covers 1024 out-float4 = 4096 floats; batch slab = 98 blocks
    int blk = blockIdx.x;
    int b   = blk / 98;
    int t   = threadIdx.x;

    __shared__ float s_sq[CC];
    __shared__ float s_hid[16];
    __shared__ float s_exc[CC];

    if (t < CC) s_sq[t] = g_squeeze[b*CC + t];
    __syncthreads();

    // hidden[j] = relu(b1[j] + sum_c sq[c]*W1[c*16+j]); 256 thr = (j<16) x (cl<16)
    {
        int j = t >> 4, cl = t & 15;
        float acc = 0.f;
        #pragma unroll
        for (int k = 0; k < 8; k++){
            int cc = cl + 16*k;
            acc += s_sq[cc] * __ldg(&W1[cc*16 + j]);
        }
        #pragma unroll
        for (int o = 8; o; o >>= 1) acc += __shfl_xor_sync(~0u, acc, o);
        if (cl == 0) s_hid[j] = fmaxf(acc + __ldg(&b1[j]), 0.f);
    }
    __syncthreads();

    if (t < CC){
        float a = __ldg(&b2[t]);
        #pragma unroll
        for (int j = 0; j < 16; j++) a += s_hid[j] * __ldg(&W2[j*CC + t]);
        s_exc[t] = __fdividef(1.f, 1.f + __expf(-a));
    }
    __syncthreads();

    const float4* exc4 = (const float4*)s_exc;
    const float4* t12_4 = (const float4*)g_t12;
    #pragma unroll
    for (int it = 0; it < 4; it++){
        int i = blk*1024 + it*256 + t;      // out float4 index
        float4 u = t12_4[2*i];              // (t1[c],t2[c],t1[c+1],t2[c+1])
        float4 v = t12_4[2*i+1];            // (t1[c+2],t2[c+2],t1[c+3],t2[c+3])
        float4 e = exc4[i & 31];
        float4 o;
        o.x = fmaf(u.y, e.x, u.x);
        o.y = fmaf(u.w, e.y, u.z);
        o.z = fmaf(v.y, e.z, v.x);
        o.w = fmaf(v.w, e.w, v.z);
        ((float4*)out)[i] = o;
    }
}

// ---------------- launch ----------------
extern "C" void kernel_launch(void* const* d_in, const int* in_sizes, int n_in,
                              void* d_out, int out_size)
{
    const float* x       = (const float*)d_in[0];
    const float* kappa   = (const float*)d_in[1];
    const float* W1      = (const float*)d_in[2];
    const float* b1      = (const float*)d_in[3];
    const float* W2      = (const float*)d_in[4];
    const float* b2      = (const float*)d_in[5];
    const float* gamma   = (const float*)d_in[6];
    const float* beta    = (const float*)d_in[7];
    const float* bn_mean = (const float*)d_in[8];
    const float* bn_var  = (const float*)d_in[9];

    cudaFuncSetAttribute(k_main, cudaFuncAttributeMaxDynamicSharedMemorySize, CH*CST*4);

    k_minmax<<<512, 256>>>(x, kappa);
    dim3 gb(CC/CH, BB);
    k_main<<<gb, 512, CH*CST*4>>>(x, gamma, beta, bn_mean, bn_var);
    k_final<<<NELEM/4096, 256>>>((float*)d_out, W1, b1, W2, b2);
}

// round 9
// speedup vs baseline: 1.5591x; 1.4531x over previous
#include <cuda_runtime.h>
#include <cuda_fp16.h>
#include <math.h>

#define BB 16
#define HH 56
#define WW 56
#define CC 128
#define HW 3136
#define NELEM (BB*HW*CC)   // 6422528
#define CH 8               // channels per block in main kernel
#define CST 3300           // padded per-channel SAT stride (floats); 3300 % 32 == 4

// ---------------- device scratch (no allocation allowed) ----------------
__device__ uint4  g_t12h[NELEM/4];    // packed half2(t1,t2) per element, 16B-aligned
__device__ float  g_squeeze[BB*CC];
__device__ float  g_pmin[BB*28];
__device__ float  g_pmax[BB*28];
__device__ float  g_bv[5];
__device__ float  g_nbv;

// ---------------- kernel A: per-batch partial min/max + scale constants ----------------
// 448 blocks = 16 batches x 28 subs; each thread: 14 fully-unrolled independent float4 loads
__global__ void __launch_bounds__(256) k_minmax(const float* __restrict__ x,
                                                const float* __restrict__ kappa){
    int b = blockIdx.x / 28, sub = blockIdx.x % 28;
    const float4* xb = (const float4*)(x + (size_t)b*HW*CC);
    int base = sub*3584 + threadIdx.x;          // 3584 float4 per sub-block
    float mn0=3.4e38f, mn1=3.4e38f, mn2=3.4e38f, mn3=3.4e38f;
    float mx0=-3.4e38f, mx1=-3.4e38f, mx2=-3.4e38f, mx3=-3.4e38f;
    #pragma unroll
    for (int k = 0; k < 14; k++){
        float4 v = xb[base + k*256];
        mn0 = fminf(mn0, v.x); mx0 = fmaxf(mx0, v.x);
        mn1 = fminf(mn1, v.y); mx1 = fmaxf(mx1, v.y);
        mn2 = fminf(mn2, v.z); mx2 = fmaxf(mx2, v.z);
        mn3 = fminf(mn3, v.w); mx3 = fmaxf(mx3, v.w);
    }
    float mn = fminf(fminf(mn0,mn1), fminf(mn2,mn3));
    float mx = fmaxf(fmaxf(mx0,mx1), fmaxf(mx2,mx3));
    #pragma unroll
    for (int o = 16; o; o >>= 1){
        mn = fminf(mn, __shfl_xor_sync(~0u, mn, o));
        mx = fmaxf(mx, __shfl_xor_sync(~0u, mx, o));
    }
    __shared__ float smn[8], smx[8];
    int lane = threadIdx.x & 31, wp = threadIdx.x >> 5;
    if (lane == 0){ smn[wp] = mn; smx[wp] = mx; }
    __syncthreads();
    if (threadIdx.x == 0){
        for (int i = 1; i < 8; i++){ mn = fminf(mn, smn[i]); mx = fmaxf(mx, smx[i]); }
        g_pmin[b*28+sub] = mn;
        g_pmax[b*28+sub] = mx;
    }
    if (blockIdx.x == 0 && threadIdx.x == 32){
        const float LN2 = 0.6931471805599453f;
        float v[5]; float mean = 0.f;
        for (int s = 0; s < 5; s++){
            float kk   = 1.f/(1.f + expf(-kappa[s]));
            float lk   = logf(kk + 1e-7f);
            float logk = 1.f/(1.f + expf(-lk));
            v[s] = logk + (float)(s+1)*LN2;        // log_k + log_r
            mean += v[s];
        }
        mean *= 0.2f;
        float bv[5]; float bsum = 0.f;
        for (int s = 0; s < 5; s++){ bv[s] = v[s]-mean; bsum += bv[s]; }
        bsum *= 0.2f;                               // force sum(bv) == 0 exactly
        float n2 = 0.f;
        for (int s = 0; s < 5; s++){ bv[s] -= bsum; g_bv[s] = bv[s]; n2 += bv[s]*bv[s]; }
        g_nbv = sqrtf(n2);
    }
}

// ---------------- kernel B: SAT + alphas + sim, emit packed t12 + squeeze ----------------
__global__ void __launch_bounds__(512) k_main(
    const float* __restrict__ x,
    const float* __restrict__ gamma, const float* __restrict__ beta,
    const float* __restrict__ bn_mean, const float* __restrict__ bn_var)
{
    extern __shared__ float sat[];      // CH * CST floats
    int b  = blockIdx.y;
    int c0 = blockIdx.x * CH;
    int t  = threadIdx.x;               // 512
    int ci = t & 7;
    int c  = c0 + ci;

    // reduce the 28 partial min/max for this batch (warp 0)
    __shared__ float s_mm[2];
    if (t < 32){
        float mnv = (t < 28) ? g_pmin[b*28 + t] :  3.4e38f;
        float mxv = (t < 28) ? g_pmax[b*28 + t] : -3.4e38f;
        #pragma unroll
        for (int o = 16; o; o >>= 1){
            mnv = fminf(mnv, __shfl_xor_sync(~0u, mnv, o));
            mxv = fmaxf(mxv, __shfl_xor_sync(~0u, mxv, o));
        }
        if (t == 0){ s_mm[0] = mnv; s_mm[1] = mxv; }
    }
    // zero SAT borders (row 0, col 0 of each 57x57 table); CH*57 = 456 < 512
    if (t < CH*57){
        int cc = t/57, j = t%57;
        sat[cc*CST + j]      = 0.f;     // row 0
        sat[cc*CST + j*57]   = 0.f;     // col 0
    }
    __syncthreads();
    float xmin = s_mm[0];
    float xmax = s_mm[1];
    float inv  = 1.f/(xmax - xmin + 1e-7f);
    const float* xb = x + (size_t)b*HW*CC;

    // load normalized xs into SAT interior (coalesced: 8 consecutive channels per pixel)
    for (int idx = t; idx < HW*CH; idx += 512){
        int cc = idx & 7; int p = idx >> 3;
        int h = p/56, w = p - h*56;
        float v = (xb[p*CC + c0 + cc] - xmin) * inv;
        sat[cc*CST + (h+1)*57 + (w+1)] = v;
    }
    __syncthreads();

    // row prefix sums (448 rows, one per thread)
    if (t < 448){
        int cc = t/56; int i = (t%56) + 1;
        float* row = sat + cc*CST + i*57;
        float acc = 0.f;
        #pragma unroll
        for (int j = 1; j <= 56; j++){ acc += row[j]; row[j] = acc; }
    }
    __syncthreads();

    // column prefix sums (448 cols, one per thread)
    if (t < 448){
        int cc = t/56; int j = (t%56) + 1;
        float* col = sat + cc*CST + j;
        float acc = 0.f;
        #pragma unroll
        for (int i = 1; i <= 56; i++){ acc += col[i*57]; col[i*57] = acc; }
    }
    __syncthreads();

    // per-thread constants
    float bns = gamma[c] * rsqrtf(bn_var[c] + 1e-3f);
    float bnb = beta[c] - bns*bn_mean[c];
    float bv0 = g_bv[0], bv1 = g_bv[1], bv2 = g_bv[2], bv3 = g_bv[3], bv4 = g_bv[4];
    const float LN2 = 0.69314718055994531f;
    float C1  = LN2 * g_nbv;            // multiplies sqrt(na2)*|alpha|
    const float* S = sat + ci*CST;
    __half2* t12p = ((__half2*)g_t12h) + (size_t)b*HW*CC;

    float asum = 0.f;
    int p0 = t >> 3;                   // 0..63
    const int KK[5] = {2,4,8,16,32};
    const int PB[5] = {0,1,3,7,15};    // TF SAME pad_before = (k-1)/2

    for (int it = 0; it < 49; it++){
        int p = p0 + it*64;
        int h = p/56, w = p - h*56;
        float L[5];   // log2(m + eps)  -- raw MUFU LG2, everything stays in log2 basis
        #pragma unroll
        for (int s = 0; s < 5; s++){
            int r0 = max(h - PB[s], 0), r1 = min(h - PB[s] + KK[s], 56);
            int q0 = max(w - PB[s], 0), q1 = min(w - PB[s] + KK[s], 56);
            float m = S[r1*57 + q1] - S[r0*57 + q1] - S[r1*57 + q0] + S[r0*57 + q0];
            L[s] = __log2f(m + 1e-7f);
        }
        float sumL = (L[0]+L[1]) + (L[2]+L[3]) + L[4];
        // alpha (natural-log OLS slope) == 0.1*(2(L4-L0)+(L3-L1)) in log2 basis
        float alpha = 0.1f * (2.f*(L[4]-L[0]) + (L[3]-L[1]));
        // dot(a,bv) = sum(L*bv) since sum(bv)==0 ;  |a|^2 = sum(L^2) - (sum L)^2/5
        float dotv = L[0]*bv0 + L[1]*bv1 + L[2]*bv2 + L[3]*bv3 + L[4]*bv4;
        float sq   = L[0]*L[0] + L[1]*L[1] + L[2]*L[2] + L[3]*L[3] + L[4]*L[4];
        float na2  = fmaxf(fmaf(-0.2f*sumL, sumL, sq), 0.f);
        float rs   = rsqrtf(na2 + 1e-20f);
        float sqn  = na2 * rs;                              // sqrt(na2), ==0 when na2==0
        float denom = fmaf(sqn * fabsf(alpha), C1, 1e-7f);
        float cosv  = __fdividef(LN2 * alpha * dotv, denom);
        float sim   = fmaf(cosv, 0.5f, 0.5f);
        float sg    = __fdividef(1.f, 1.f + __expf(-fmaf(bns, alpha, bnb)));
        float xs    = (__ldg(&xb[p*CC + c]) - xmin) * inv;  // L2-hit re-read
        t12p[p*CC + c] = __floats2half2_rn(sim * sg, (1.f - sim) * xs);
        asum += alpha;
    }

    // per-channel alpha sum -> squeeze (block owns full H*W of its 8 channels)
    asum += __shfl_xor_sync(~0u, asum, 8);
    asum += __shfl_xor_sync(~0u, asum, 16);
    __shared__ float red[16][8];
    int lane = t & 31, wp = t >> 5;
    if (lane < 8) red[wp][lane] = asum;
    __syncthreads();
    if (t < 8){
        float s = 0.f;
        #pragma unroll
        for (int i = 0; i < 16; i++) s += red[i][t];
        g_squeeze[b*CC + c0 + t] = s * (1.f/3136.f);
    }
}

// ---------------- kernel C: per-block SE-MLP (smem) + final blend ----------------
__global__ void __launch_bounds__(256) k_final(
    float* __restrict__ out,
    const float* __restrict__ W1, const float* __restrict__ b1,
    const float* __restrict__ W2, const float* __restrict__ b2)
{
    // each block covers 1024 out-float4 = 4096 floats; batch slab = 98 blocks
    int blk = blockIdx.x;
    int b   = blk / 98;
    int t   = threadIdx.x;

    __shared__ float s_sq[CC];
    __shared__ float s_hid[16];
    __shared__ float s_exc[CC];

    if (t < CC) s_sq[t] = g_squeeze[b*CC + t];
    __syncthreads();

    // hidden[j] = relu(b1[j] + sum_c sq[c]*W1[c*16+j]); 256 thr = (j<16) x (cl<16)
    {
        int j = t >> 4, cl = t & 15;
        float acc = 0.f;
        #pragma unroll
        for (int k = 0; k < 8; k++){
            int cc = cl + 16*k;
            acc += s_sq[cc] * __ldg(&W1[cc*16 + j]);
        }
        #pragma unroll
        for (int o = 8; o; o >>= 1) acc += __shfl_xor_sync(~0u, acc, o);
        if (cl == 0) s_hid[j] = fmaxf(acc + __ldg(&b1[j]), 0.f);
    }
    __syncthreads();

    if (t < CC){
        float a = __ldg(&b2[t]);
        #pragma unroll
        for (int j = 0; j < 16; j++) a += s_hid[j] * __ldg(&W2[j*CC + t]);
        s_exc[t] = __fdividef(1.f, 1.f + __expf(-a));
    }
    __syncthreads();

    const float4* exc4 = (const float4*)s_exc;
    #pragma unroll
    for (int it = 0; it < 4; it++){
        int i = blk*1024 + it*256 + t;      // out float4 index (4 channels)
        uint4 u = g_t12h[i];                // 4 x half2(t1,t2)
        float2 p0 = __half22float2(*(__half2*)&u.x);
        float2 p1 = __half22float2(*(__half2*)&u.y);
        float2 p2 = __half22float2(*(__half2*)&u.z);
        float2 p3 = __half22float2(*(__half2*)&u.w);
        float4 e = exc4[i & 31];
        float4 o;
        o.x = fmaf(p0.y, e.x, p0.x);
        o.y = fmaf(p1.y, e.y, p1.x);
        o.z = fmaf(p2.y, e.z, p2.x);
        o.w = fmaf(p3.y, e.w, p3.x);
        ((float4*)out)[i] = o;
    }
}

// ---------------- launch ----------------
extern "C" void kernel_launch(void* const* d_in, const int* in_sizes, int n_in,
                              void* d_out, int out_size)
{
    const float* x       = (const float*)d_in[0];
    const float* kappa   = (const float*)d_in[1];
    const float* W1      = (const float*)d_in[2];
    const float* b1      = (const float*)d_in[3];
    const float* W2      = (const float*)d_in[4];
    const float* b2      = (const float*)d_in[5];
    const float* gamma   = (const float*)d_in[6];
    const float* beta    = (const float*)d_in[7];
    const float* bn_mean = (const float*)d_in[8];
    const float* bn_var  = (const float*)d_in[9];

    cudaFuncSetAttribute(k_main, cudaFuncAttributeMaxDynamicSharedMemorySize, CH*CST*4);

    k_minmax<<<448, 256>>>(x, kappa);
    dim3 gb(CC/CH, BB);
    k_main<<<gb, 512, CH*CST*4>>>(x, gamma, beta, bn_mean, bn_var);
    k_final<<<NELEM/4096, 256>>>((float*)d_out, W1, b1, W2, b2);
}